// round 2
// baseline (speedup 1.0000x reference)
#include <cuda_runtime.h>
#include <cmath>

// Problem constants (fixed by the dataset)
#define T_TOK 1024
#define H_DIM 2048
#define I_DIM 768
#define E_NUM 8
#define K_TOP 2
#define NROWS (T_TOK * K_TOP)      // 2048 permuted rows

// Tiling
#define BM 64
#define BN 64
#define BK 16
#define MAX_TILES 40               // sum_e ceil(cnt_e/64) <= 32 + 7 = 39

// ---------------- scratch (no allocations allowed) ----------------
__device__ int   g_row_src[NROWS];        // sorted-position -> flat (t*K + k)
__device__ int   g_tile_expert[MAX_TILES];
__device__ int   g_tile_row[MAX_TILES];   // global row start of this M-tile
__device__ int   g_tile_end[MAX_TILES];   // end row of this expert's group
__device__ int   g_num_tiles;
__device__ float g_act[NROWS * I_DIM];    // swiglu output [2048, 768]

// ---------------- zero the output (it is poisoned) ----------------
__global__ void zero_kernel(float* __restrict__ out, int n4) {
    int i = blockIdx.x * blockDim.x + threadIdx.x;
    int stride = gridDim.x * blockDim.x;
    float4 z = make_float4(0.f, 0.f, 0.f, 0.f);
    for (; i < n4; i += stride)
        reinterpret_cast<float4*>(out)[i] = z;
}

// ---------------- setup: counting sort by expert + tile descriptors ----------------
__global__ void setup_kernel(const int* __restrict__ sel) {
    __shared__ int cnt[E_NUM];
    __shared__ int run[E_NUM];
    int tid = threadIdx.x;
    if (tid < E_NUM) cnt[tid] = 0;
    __syncthreads();
    for (int i = tid; i < NROWS; i += blockDim.x)
        atomicAdd(&cnt[sel[i]], 1);
    __syncthreads();
    if (tid == 0) {
        int s = 0, nt = 0;
        for (int e = 0; e < E_NUM; e++) {
            run[e] = s;
            int c = cnt[e];
            for (int r = 0; r < c; r += BM) {
                g_tile_expert[nt] = e;
                g_tile_row[nt]    = s + r;
                g_tile_end[nt]    = s + c;
                nt++;
            }
            s += c;
        }
        g_num_tiles = nt;
    }
    __syncthreads();
    for (int i = tid; i < NROWS; i += blockDim.x) {
        int e = sel[i];
        int p = atomicAdd(&run[e], 1);
        g_row_src[p] = i;
    }
}

// ---------------- GEMM1: act = swiglu( X_gather @ W1[e] ) ----------------
// Block: BM rows x BN cols of the I-dim (computes gate col j AND up col j+I fused).
__global__ void __launch_bounds__(256)
gemm1_kernel(const float* __restrict__ x, const float* __restrict__ w1) {
    int mt = blockIdx.x;
    if (mt >= g_num_tiles) return;
    int e    = g_tile_expert[mt];
    int row0 = g_tile_row[mt];
    int rend = g_tile_end[mt];
    int col0 = blockIdx.y * BN;                 // 0 .. I_DIM-BN

    const float* W = w1 + (size_t)e * H_DIM * (2 * I_DIM);

    __shared__ float As[BK][BM];
    __shared__ float Ba[BK][BN];
    __shared__ float Bb[BK][BN];
    __shared__ int   s_tok[BM];

    int tid = threadIdx.x;
    if (tid < BM) {
        int r = row0 + tid;
        s_tok[tid] = (r < rend) ? (g_row_src[r] / K_TOP) : -1;
    }
    __syncthreads();

    float accA[4][4] = {}, accB[4][4] = {};
    int ty = tid >> 4, tx = tid & 15;

    // A-load mapping: one float4 per thread. r = tid/4, kk = (tid%4)*4
    int ar  = tid >> 2;
    int akk = (tid & 3) * 4;
    // B-load mapping: one float4 per thread per tile. kk = tid/16, c = (tid%16)*4
    int bkk = tid >> 4;
    int bc  = (tid & 15) * 4;

    for (int k0 = 0; k0 < H_DIM; k0 += BK) {
        // ---- load A 64x16 (gathered rows) ----
        {
            int tok = s_tok[ar];
            float4 v = make_float4(0.f, 0.f, 0.f, 0.f);
            if (tok >= 0)
                v = *reinterpret_cast<const float4*>(&x[(size_t)tok * H_DIM + k0 + akk]);
            As[akk + 0][ar] = v.x;
            As[akk + 1][ar] = v.y;
            As[akk + 2][ar] = v.z;
            As[akk + 3][ar] = v.w;
        }
        // ---- load B (gate and up) 16x64 each ----
        {
            const float* wr = W + (size_t)(k0 + bkk) * (2 * I_DIM);
            float4 va = *reinterpret_cast<const float4*>(&wr[col0 + bc]);
            float4 vb = *reinterpret_cast<const float4*>(&wr[I_DIM + col0 + bc]);
            *reinterpret_cast<float4*>(&Ba[bkk][bc]) = va;
            *reinterpret_cast<float4*>(&Bb[bkk][bc]) = vb;
        }
        __syncthreads();

        #pragma unroll
        for (int kk = 0; kk < BK; kk++) {
            float4 a4  = *reinterpret_cast<const float4*>(&As[kk][ty * 4]);
            float4 ba4 = *reinterpret_cast<const float4*>(&Ba[kk][tx * 4]);
            float4 bb4 = *reinterpret_cast<const float4*>(&Bb[kk][tx * 4]);
            float a[4]  = {a4.x, a4.y, a4.z, a4.w};
            float ba[4] = {ba4.x, ba4.y, ba4.z, ba4.w};
            float bb[4] = {bb4.x, bb4.y, bb4.z, bb4.w};
            #pragma unroll
            for (int i = 0; i < 4; i++)
                #pragma unroll
                for (int j = 0; j < 4; j++) {
                    accA[i][j] = fmaf(a[i], ba[j], accA[i][j]);
                    accB[i][j] = fmaf(a[i], bb[j], accB[i][j]);
                }
        }
        __syncthreads();
    }

    // epilogue: swiglu
    #pragma unroll
    for (int i = 0; i < 4; i++) {
        int r = row0 + ty * 4 + i;
        if (r < rend) {
            #pragma unroll
            for (int j = 0; j < 4; j++) {
                float g = accA[i][j];
                float sig = 1.0f / (1.0f + expf(-g));
                g_act[(size_t)r * I_DIM + col0 + tx * 4 + j] = g * sig * accB[i][j];
            }
        }
    }
}

// ---------------- GEMM2: out[t] += w[t,k] * (act @ W2[e]) ----------------
__global__ void __launch_bounds__(256)
gemm2_kernel(const float* __restrict__ w2, const float* __restrict__ rw,
             float* __restrict__ out) {
    int mt = blockIdx.x;
    if (mt >= g_num_tiles) return;
    int e    = g_tile_expert[mt];
    int row0 = g_tile_row[mt];
    int rend = g_tile_end[mt];
    int col0 = blockIdx.y * BN;                 // 0 .. H_DIM-BN

    const float* W = w2 + (size_t)e * I_DIM * H_DIM;

    __shared__ float As[BK][BM];
    __shared__ float Bs[BK][BN];
    __shared__ int   s_src[BM];

    int tid = threadIdx.x;
    if (tid < BM) {
        int r = row0 + tid;
        s_src[tid] = (r < rend) ? g_row_src[r] : -1;
    }
    __syncthreads();

    float acc[4][4] = {};
    int ty = tid >> 4, tx = tid & 15;
    int ar  = tid >> 2;
    int akk = (tid & 3) * 4;
    int bkk = tid >> 4;
    int bc  = (tid & 15) * 4;

    for (int k0 = 0; k0 < I_DIM; k0 += BK) {
        {
            int src = s_src[ar];
            float4 v = make_float4(0.f, 0.f, 0.f, 0.f);
            if (src >= 0) {
                int rr = row0 + ar;
                v = *reinterpret_cast<const float4*>(&g_act[(size_t)rr * I_DIM + k0 + akk]);
            }
            As[akk + 0][ar] = v.x;
            As[akk + 1][ar] = v.y;
            As[akk + 2][ar] = v.z;
            As[akk + 3][ar] = v.w;
        }
        {
            float4 v = *reinterpret_cast<const float4*>(
                &W[(size_t)(k0 + bkk) * H_DIM + col0 + bc]);
            *reinterpret_cast<float4*>(&Bs[bkk][bc]) = v;
        }
        __syncthreads();

        #pragma unroll
        for (int kk = 0; kk < BK; kk++) {
            float4 a4 = *reinterpret_cast<const float4*>(&As[kk][ty * 4]);
            float4 b4 = *reinterpret_cast<const float4*>(&Bs[kk][tx * 4]);
            float a[4] = {a4.x, a4.y, a4.z, a4.w};
            float b[4] = {b4.x, b4.y, b4.z, b4.w};
            #pragma unroll
            for (int i = 0; i < 4; i++)
                #pragma unroll
                for (int j = 0; j < 4; j++)
                    acc[i][j] = fmaf(a[i], b[j], acc[i][j]);
        }
        __syncthreads();
    }

    #pragma unroll
    for (int i = 0; i < 4; i++) {
        int r = row0 + ty * 4 + i;
        if (r < rend) {
            int src = s_src[ty * 4 + i];
            int t  = src / K_TOP;
            int kk = src - t * K_TOP;
            float w = rw[t * K_TOP + kk];
            #pragma unroll
            for (int j = 0; j < 4; j++)
                atomicAdd(&out[(size_t)t * H_DIM + col0 + tx * 4 + j], w * acc[i][j]);
        }
    }
}

// ---------------- launch ----------------
extern "C" void kernel_launch(void* const* d_in, const int* in_sizes, int n_in,
                              void* d_out, int out_size) {
    const float* x   = (const float*)d_in[0];   // hidden_states [T, H]
    const float* rw  = (const float*)d_in[1];   // routing_weights [T, K]
    const float* w1  = (const float*)d_in[2];   // gate_up_proj [E, H, 2I]
    const float* w2  = (const float*)d_in[3];   // down_proj   [E, I, H]
    const int*   sel = (const int*)d_in[4];     // selected_experts [T, K]
    float* out = (float*)d_out;                 // [T, H] fp32

    zero_kernel<<<512, 256>>>(out, (T_TOK * H_DIM) / 4);
    setup_kernel<<<1, 256>>>(sel);
    gemm1_kernel<<<dim3(MAX_TILES, I_DIM / BN), 256>>>(x, w1);
    gemm2_kernel<<<dim3(MAX_TILES, H_DIM / BN), 256>>>(w2, rw, out);
}